// round 7
// baseline (speedup 1.0000x reference)
#include <cuda_runtime.h>
#include <cuda_fp16.h>
#include <cstdint>

// Problem constants
#define NN 1024   // nodes
#define NB 8      // batch
#define NS 64     // timesteps
#define NH 32     // hidden

// GEMM tiling: per CTA, M=128 (n rows) x N=256 cols (2u x 64t x 2 gates), K=1024
#define BK 64
#define NKT 16           // k-iters

// SMEM layout (bytes)
#define AP 88            // opA pitch (halfs): frag-LDS and STS both at bank floor
#define BP 88            // opB pitch (halfs)
#define RAP 272          // rawA row pitch bytes (68 floats)
#define RXP 144          // rawX row pitch bytes (32 half2 data + pad)
#define OPA_B (128 * AP * 2)   // 22528
#define OPB_B (256 * BP * 2)   // 45056
#define OFF_WH   0                         // 4 x 1024 halfs = 8192
#define OFF_RAWA 8192                      // 128 * 272 = 34816
#define OFF_RAWX (OFF_RAWA + 34816)        // 43008; 64 * 144 = 9216
#define OFF_OPA  (OFF_RAWX + 9216)         // 52224; 2 x 22528
#define OFF_OPB  (OFF_OPA + 2 * OPA_B)     // 97280; 2 x 45056
#define SMEM_BYTES (OFF_OPB + 2 * OPB_B)   // 187392  (Z epilogue 131584 aliases)
#define ZPITCH 257

// Global scratch
__device__ __half2 g_xh[(size_t)NB * NS * (NN / 2)];   // xh[b][t][m/2]  (transposed X)
__device__ float   g_h[NB * NN * NH];

// ---------------- helpers ----------------
__device__ __forceinline__ uint32_t smem_u32(const void* p) {
    uint32_t a;
    asm("{ .reg .u64 t; cvta.to.shared.u64 t, %1; cvt.u32.u64 %0, t; }" : "=r"(a) : "l"(p));
    return a;
}
__device__ __forceinline__ void cp16(uint32_t s, const void* g) {
    asm volatile("cp.async.cg.shared.global [%0], [%1], 16;" :: "r"(s), "l"(g) : "memory");
}
__device__ __forceinline__ void cp_commit() {
    asm volatile("cp.async.commit_group;" ::: "memory");
}
template <int N>
__device__ __forceinline__ void cp_wait() {
    asm volatile("cp.async.wait_group %0;" :: "n"(N) : "memory");
}
__device__ __forceinline__ void mma_f16(float c[4], uint2 alo, uint2 ahi, uint2 bf) {
    asm volatile(
        "mma.sync.aligned.m16n8k16.row.col.f32.f16.f16.f32 "
        "{%0,%1,%2,%3}, {%4,%5,%6,%7}, {%8,%9}, {%0,%1,%2,%3};\n"
        : "+f"(c[0]), "+f"(c[1]), "+f"(c[2]), "+f"(c[3])
        : "r"(alo.x), "r"(ahi.x), "r"(alo.y), "r"(ahi.y), "r"(bf.x), "r"(bf.y));
}
__device__ __forceinline__ uint32_t pack2(float a, float b) {
    __half2 h = __halves2half2(__float2half_rn(a), __float2half_rn(b));
    return *reinterpret_cast<uint32_t*>(&h);
}

// ---------------- prep: xh[b][t][m/2] = half2(X[b,2m2,t], X[b,2m2+1,t]) ----------------
__global__ void xh_kernel(const float* __restrict__ X) {
    int idx = blockIdx.x * 256 + threadIdx.x;   // 262,144
    int m2 = idx & 511;
    int t  = (idx >> 9) & 63;
    int b  = idx >> 15;
    const float* src = X + (size_t)b * NN * NS + (size_t)(2 * m2) * NS + t;
    g_xh[(size_t)(b * NS + t) * 512 + m2] =
        __halves2half2(__float2half_rn(src[0]), __float2half_rn(src[NS]));
}

// ---------------- main: fused convert + fp16 HMMA GEMM + GRU scan ----------------
__global__ void __launch_bounds__(256, 1)
gemm_gru_kernel(const float* __restrict__ G,   // (B, N, N)
                const float* __restrict__ Wu, const float* __restrict__ bu,
                const float* __restrict__ Wc, const float* __restrict__ bc,
                const float* __restrict__ h0)
{
    extern __shared__ __align__(16) char smem[];
    const uint32_t sb = smem_u32(smem);

    const int tid  = threadIdx.x;
    const int wid  = tid >> 5;
    const int lane = tid & 31;
    const int wm   = wid >> 2;
    const int wn   = wid & 3;
    const int grp  = lane >> 2;
    const int qid  = lane & 3;

    const int mt = blockIdx.x;    // n-tile (8)
    const int nt = blockIdx.y;    // u-pair (16)
    const int b  = blockIdx.z;
    const int u0 = nt * 2;

    const char* gA = (const char*)(G + ((size_t)b * NN + mt * 128) * NN);

    // ---- prologue: stage the 4 weight rows (u0/u0+1 x u-gate/c-gate) into smem ----
    {
        int widx = tid >> 6;               // 0..3 = gate*2 + ul
        int gate = widx >> 1, ul = widx & 1;
        int j = (tid & 63) * 16;           // 16 halfs per thread
        const float* wsrc = (gate ? Wc : Wu) + (size_t)(u0 + ul) * NN + j;
        uint32_t wd = sb + OFF_WH + (widx * 1024 + j) * 2;
        float4 f0 = *(const float4*)(wsrc + 0);
        float4 f1 = *(const float4*)(wsrc + 4);
        float4 f2 = *(const float4*)(wsrc + 8);
        float4 f3 = *(const float4*)(wsrc + 12);
        uint4 o0 = make_uint4(pack2(f0.x, f0.y), pack2(f0.z, f0.w),
                              pack2(f1.x, f1.y), pack2(f1.z, f1.w));
        uint4 o1 = make_uint4(pack2(f2.x, f2.y), pack2(f2.z, f2.w),
                              pack2(f3.x, f3.y), pack2(f3.z, f3.w));
        *(uint4*)(smem + (wd - sb))      = o0;
        *(uint4*)(smem + (wd - sb) + 16) = o1;
    }

    // B-convert identity: thread owns output column
    const int col  = tid;
    const int ul_c = col >> 7;
    const int tt   = (col & 127) >> 1;
    const int gate = col & 1;
    const int widx = gate * 2 + ul_c;
    const __half2* xsrc = g_xh + (size_t)(b * NS + tt) * 512;   // + kt*32 per iter

    float acc[4][8][4];
#pragma unroll
    for (int i = 0; i < 4; i++)
#pragma unroll
        for (int j = 0; j < 8; j++)
#pragma unroll
            for (int r = 0; r < 4; r++) acc[i][j][r] = 0.f;

// issue cp.async for raw G slice (32KB) + raw xh slice (8KB) of chunk KT
#define ISSUE_RAW(KT) do {                                                         \
    _Pragma("unroll")                                                              \
    for (int i = 0; i < 8; i++) {                                                  \
        int q = tid + i * 256;                                                     \
        int row = q >> 4, j = q & 15;                                              \
        cp16(sb + OFF_RAWA + row * RAP + j * 16,                                   \
             gA + (size_t)row * 4096 + (KT) * 256 + j * 16);                       \
    }                                                                              \
    _Pragma("unroll")                                                              \
    for (int i = 0; i < 2; i++) {                                                  \
        int q = tid + i * 256;                                                     \
        int t = q >> 3, j = q & 7;                                                 \
        cp16(sb + OFF_RAWX + t * RXP + j * 16,                                     \
             (const char*)(xsrc - (size_t)tt * 512 + (size_t)t * 512 + (KT) * 32) + j * 16); \
    }                                                                              \
    cp_commit();                                                                   \
} while (0)

// convert raw fp32 G -> opA halfs (fragment-permuted), and build opB = wh*xh
#define CONVERT(BUF) do {                                                          \
    {   /* A: thread = (row = tid>>1, k-half = tid&1) */                           \
        int row = tid >> 1;                                                        \
        int kh  = tid & 1;                                                         \
        const float* rp = (const float*)(smem + OFF_RAWA + row * RAP) + kh * 32;   \
        char* od = smem + OFF_OPA + (BUF) * OPA_B + row * (AP * 2) + kh * 64;      \
        _Pragma("unroll")                                                          \
        for (int ks2 = 0; ks2 < 2; ks2++) {                                        \
            float4 f0 = *(const float4*)(rp + ks2 * 16 + 0);                       \
            float4 f1 = *(const float4*)(rp + ks2 * 16 + 4);                       \
            float4 f2 = *(const float4*)(rp + ks2 * 16 + 8);                       \
            float4 f3 = *(const float4*)(rp + ks2 * 16 + 12);                      \
            uint4 o0 = make_uint4(pack2(f0.x, f0.y), pack2(f2.x, f2.y),            \
                                  pack2(f0.z, f0.w), pack2(f2.z, f2.w));           \
            uint4 o1 = make_uint4(pack2(f1.x, f1.y), pack2(f3.x, f3.y),            \
                                  pack2(f1.z, f1.w), pack2(f3.z, f3.w));           \
            *(uint4*)(od + ks2 * 32)      = o0;                                    \
            *(uint4*)(od + ks2 * 32 + 16) = o1;                                    \
        }                                                                          \
    }                                                                              \
    {   /* B: thread = col; r[j] = wh2[j] * xh2[j], j = k/2 in chunk */            \
        const uint32_t* xr = (const uint32_t*)(smem + OFF_RAWX + tt * RXP);        \
        const uint32_t* wr = (const uint32_t*)(smem + OFF_WH + widx * 2048) + 16 * 0; \
        uint32_t r[32];                                                            \
        _Pragma("unroll")                                                          \
        for (int j = 0; j < 32; j++) {                                             \
            __half2 wv = *(const __half2*)(wr + kchunk_off + j);                   \
            __half2 xv = *(const __half2*)(xr + j);                                \
            __half2 pv = __hmul2(wv, xv);                                          \
            r[j] = *reinterpret_cast<uint32_t*>(&pv);                              \
        }                                                                          \
        char* od = smem + OFF_OPB + (BUF) * OPB_B + col * (BP * 2);                \
        _Pragma("unroll")                                                          \
        for (int ks = 0; ks < 4; ks++) {                                           \
            int j0 = ks * 8;                                                       \
            uint4 o0 = make_uint4(r[j0 + 0], r[j0 + 4], r[j0 + 1], r[j0 + 5]);     \
            uint4 o1 = make_uint4(r[j0 + 2], r[j0 + 6], r[j0 + 3], r[j0 + 7]);     \
            *(uint4*)(od + ks * 32)      = o0;                                     \
            *(uint4*)(od + ks * 32 + 16) = o1;                                     \
        }                                                                          \
    }                                                                              \
} while (0)

#define COMPUTE(BUF) do {                                                          \
    const __half* Ab = (const __half*)(smem + OFF_OPA + (BUF) * OPA_B);            \
    const __half* Bb = (const __half*)(smem + OFF_OPB + (BUF) * OPB_B);            \
    _Pragma("unroll")                                                              \
    for (int ks = 0; ks < 4; ks++) {                                               \
        uint2 alo[4], ahi[4], bf[8];                                               \
        _Pragma("unroll")                                                          \
        for (int mi = 0; mi < 4; mi++) {                                           \
            const __half* ap = Ab + (wm * 64 + mi * 16 + grp) * AP + ks * 16 + qid * 4; \
            alo[mi] = *reinterpret_cast<const uint2*>(ap);                         \
            ahi[mi] = *reinterpret_cast<const uint2*>(ap + 8 * AP);                \
        }                                                                          \
        _Pragma("unroll")                                                          \
        for (int nj = 0; nj < 8; nj++)                                             \
            bf[nj] = *reinterpret_cast<const uint2*>(                              \
                Bb + (wn * 64 + nj * 8 + grp) * BP + ks * 16 + qid * 4);           \
        _Pragma("unroll")                                                          \
        for (int mi = 0; mi < 4; mi++)                                             \
        _Pragma("unroll")                                                          \
        for (int nj = 0; nj < 8; nj++)                                             \
            mma_f16(acc[mi][nj], alo[mi], ahi[mi], bf[nj]);                        \
    }                                                                              \
} while (0)

    ISSUE_RAW(0);

#pragma unroll 1
    for (int kt = 0; kt < NKT; kt++) {
        const int kchunk_off = kt * 32;   // wh half2 offset for this chunk
        cp_wait<0>();
        __syncthreads();                  // raw kt visible; prev COMPUTE done reading op[kt&1]
        CONVERT(kt & 1);
        __syncthreads();                  // op[kt&1] published; raw fully consumed
        if (kt + 1 < NKT) ISSUE_RAW(kt + 1);
        COMPUTE(kt & 1);
    }
    __syncthreads();   // all COMPUTE done before Z aliases staging smem

    // ---- Epilogue: dump Z to smem, run the GRU recurrence over t ----
    float* Zs = (float*)smem;   // [128][ZPITCH]
#pragma unroll
    for (int mi = 0; mi < 4; mi++)
#pragma unroll
        for (int nj = 0; nj < 8; nj++)
#pragma unroll
            for (int r = 0; r < 4; r++) {
                int row = wm * 64 + mi * 16 + grp + ((r >> 1) ? 8 : 0);
                int zcol = wn * 64 + nj * 8 + qid * 2 + (r & 1);
                Zs[row * ZPITCH + zcol] = acc[mi][nj][r];
            }
    __syncthreads();

    {
        const int row = tid & 127;
        const int ul  = tid >> 7;
        const int n   = mt * 128 + row;
        const int u   = u0 + ul;
        float h = h0[(size_t)u * NN + n];
        const float buv = bu[u];
        const float bcv = bc[u];
        const float* zrow = Zs + row * ZPITCH + ul * 128;
#pragma unroll 1
        for (int t = 0; t < NS; t++) {
            float zu = zrow[2 * t]     + buv;
            float zc = zrow[2 * t + 1] + bcv;
            float ug = 1.f / (1.f + __expf(-zu));
            float cg = tanhf(zc);
            h = fmaf(ug, h - cg, cg);
        }
        g_h[((size_t)b * NN + n) * NH + u] = h;
    }
#undef ISSUE_RAW
#undef CONVERT
#undef COMPUTE
}

// ---------------- prediction head ----------------
#define W1T_PITCH 33
__global__ void __launch_bounds__(256)
head_kernel(const float* __restrict__ W1, const float* __restrict__ b1,
            const float* __restrict__ W2, const float* __restrict__ b2,
            const float* __restrict__ Wd, const float* __restrict__ bd,
            float* __restrict__ out)
{
    __shared__ float w1t[NH * W1T_PITCH];
    __shared__ float w2t[2 * NH * W1T_PITCH];
    __shared__ float b1s[NH], b2s[NH];

    const int tid = threadIdx.x;
    for (int i = tid; i < NH * NH; i += 256) {
        int u = i >> 5, k = i & 31;
        w1t[k * W1T_PITCH + u] = W1[i];
    }
    for (int i = tid; i < NH * 2 * NH; i += 256) {
        int u = i >> 6, k = i & 63;
        w2t[k * W1T_PITCH + u] = W2[i];
    }
    if (tid < NH) { b1s[tid] = b1[tid]; b2s[tid] = b2[tid]; }
    __syncthreads();

    const int warp = (blockIdx.x * blockDim.x + tid) >> 5;
    const int lane = tid & 31;
    if (warp >= NB * NN) return;
    const int b = warp >> 10;
    const int n = warp & (NN - 1);

    const float hv = g_h[((size_t)b * NN + n) * NH + lane];

    float p0 = 0.f, p1 = 0.f, p2 = 0.f, p3 = 0.f;
#pragma unroll
    for (int k = 0; k < NH; k += 4) {
        p0 = fmaf(w1t[(k + 0) * W1T_PITCH + lane], __shfl_sync(0xffffffffu, hv, k + 0), p0);
        p1 = fmaf(w1t[(k + 1) * W1T_PITCH + lane], __shfl_sync(0xffffffffu, hv, k + 1), p1);
        p2 = fmaf(w1t[(k + 2) * W1T_PITCH + lane], __shfl_sync(0xffffffffu, hv, k + 2), p2);
        p3 = fmaf(w1t[(k + 3) * W1T_PITCH + lane], __shfl_sync(0xffffffffu, hv, k + 3), p3);
    }
    float x1 = b1s[lane] + ((p0 + p1) + (p2 + p3));
    x1 = x1 >= 0.f ? x1 : 0.01f * x1;

    float q0 = 0.f, q1 = 0.f, q2 = 0.f, q3 = 0.f;
#pragma unroll
    for (int k = 0; k < NH; k += 4) {
        q0 = fmaf(w2t[(k + 0) * W1T_PITCH + lane], __shfl_sync(0xffffffffu, x1, k + 0), q0);
        q1 = fmaf(w2t[(k + 1) * W1T_PITCH + lane], __shfl_sync(0xffffffffu, x1, k + 1), q1);
        q2 = fmaf(w2t[(k + 2) * W1T_PITCH + lane], __shfl_sync(0xffffffffu, x1, k + 2), q2);
        q3 = fmaf(w2t[(k + 3) * W1T_PITCH + lane], __shfl_sync(0xffffffffu, x1, k + 3), q3);
    }
#pragma unroll
    for (int k = 0; k < NH; k += 4) {
        q0 = fmaf(w2t[(NH + k + 0) * W1T_PITCH + lane], __shfl_sync(0xffffffffu, hv, k + 0), q0);
        q1 = fmaf(w2t[(NH + k + 1) * W1T_PITCH + lane], __shfl_sync(0xffffffffu, hv, k + 1), q1);
        q2 = fmaf(w2t[(NH + k + 2) * W1T_PITCH + lane], __shfl_sync(0xffffffffu, hv, k + 2), q2);
        q3 = fmaf(w2t[(NH + k + 3) * W1T_PITCH + lane], __shfl_sync(0xffffffffu, hv, k + 3), q3);
    }
    float x2 = b2s[lane] + ((q0 + q1) + (q2 + q3));
    x2 = x2 >= 0.f ? x2 : 0.01f * x2;

    float v = Wd[(size_t)n * 2 * NH + lane] * x2
            + Wd[(size_t)n * 2 * NH + NH + lane] * hv;
#pragma unroll
    for (int o = 16; o; o >>= 1) v += __shfl_xor_sync(0xffffffffu, v, o);
    if (lane == 0) out[(size_t)b * NN + n] = v + bd[n];
}

extern "C" void kernel_launch(void* const* d_in, const int* in_sizes, int n_in,
                              void* d_out, int out_size)
{
    (void)in_sizes; (void)n_in; (void)out_size;
    const float* x  = (const float*)d_in[0];
    const float* g  = (const float*)d_in[2];
    const float* Wu = (const float*)d_in[5];
    const float* bu = (const float*)d_in[6];
    const float* Wc = (const float*)d_in[7];
    const float* bc = (const float*)d_in[8];
    const float* h0 = (const float*)d_in[9];
    const float* W1 = (const float*)d_in[10];
    const float* b1 = (const float*)d_in[11];
    const float* W2 = (const float*)d_in[12];
    const float* b2 = (const float*)d_in[13];
    const float* Wd = (const float*)d_in[14];
    const float* bd = (const float*)d_in[15];
    float* out = (float*)d_out;

    xh_kernel<<<1024, 256>>>(x);

    cudaFuncSetAttribute(gemm_gru_kernel,
                         cudaFuncAttributeMaxDynamicSharedMemorySize, SMEM_BYTES);
    dim3 grid(8, 16, NB);
    gemm_gru_kernel<<<grid, 256, SMEM_BYTES>>>(g, Wu, bu, Wc, bc, h0);

    head_kernel<<<(NB * NN) / 8, 256>>>(W1, b1, W2, b2, Wd, bd, out);
}

// round 10
// speedup vs baseline: 1.2564x; 1.2564x over previous
#include <cuda_runtime.h>
#include <cuda_fp16.h>
#include <cstdint>

// Problem constants
#define NN 1024   // nodes
#define NB 8      // batch
#define NS 64     // timesteps
#define NH 32     // hidden

// GEMM tiling: per CTA, M=128 (n rows) x N=256 cols (2u x 64t x 2 gates), K=1024
#define BK 64
#define NKT 16           // k-iters
#define STAGES 3
#define AP 80            // halfs per A row (64 data + 16 pad) -> conflict-free LDS.64
#define BP 80            // halfs per B col
#define ACHUNK (128 * AP)   // 10240 halfs per (tile, kchunk)
#define BCHUNK (256 * BP)   // 20480
#define ABYTES (ACHUNK * 2) // 20480 B
#define BBYTES (BCHUNK * 2) // 40960 B
#define SBYTES (ABYTES + BBYTES)        // 61440 per stage
#define ZPITCH 257
#define SMEM_BYTES (STAGES * SBYTES)    // 184320; Z tile (131584) aliases this

// Precomputed operand buffers (16B-aligned: vector ld/st + cp.async targets)
__device__ __align__(16) __half g_A[(size_t)NB * 8 * NKT * ACHUNK];    // ~21 MB
__device__ __align__(16) __half g_B[(size_t)NB * 16 * NKT * BCHUNK];   // ~84 MB
__device__ __align__(16) __half2 g_xh[(size_t)NB * NS * (NN / 2)];     // xh[b][t][m/2]
__device__ __align__(16) float  g_h[NB * NN * NH];

// ---------------- helpers ----------------
__device__ __forceinline__ uint32_t smem_u32(const void* p) {
    uint32_t a;
    asm("{ .reg .u64 t; cvta.to.shared.u64 t, %1; cvt.u32.u64 %0, t; }" : "=r"(a) : "l"(p));
    return a;
}
__device__ __forceinline__ void cp16(uint32_t s, const void* g) {
    asm volatile("cp.async.cg.shared.global [%0], [%1], 16;" :: "r"(s), "l"(g) : "memory");
}
__device__ __forceinline__ void cp_commit() {
    asm volatile("cp.async.commit_group;" ::: "memory");
}
template <int N>
__device__ __forceinline__ void cp_wait() {
    asm volatile("cp.async.wait_group %0;" :: "n"(N) : "memory");
}
__device__ __forceinline__ void mma_f16(float c[4], uint2 alo, uint2 ahi, uint2 bf) {
    asm volatile(
        "mma.sync.aligned.m16n8k16.row.col.f32.f16.f16.f32 "
        "{%0,%1,%2,%3}, {%4,%5,%6,%7}, {%8,%9}, {%0,%1,%2,%3};\n"
        : "+f"(c[0]), "+f"(c[1]), "+f"(c[2]), "+f"(c[3])
        : "r"(alo.x), "r"(ahi.x), "r"(alo.y), "r"(ahi.y), "r"(bf.x), "r"(bf.y));
}
__device__ __forceinline__ uint32_t pack2(float a, float b) {
    __half2 h = __halves2half2(__float2half_rn(a), __float2half_rn(b));
    return *reinterpret_cast<uint32_t*>(&h);
}

// ---------------- prep: xh[b][t][m/2] via coalesced smem transpose ----------------
// Pitch 68 floats: 272 B rows keep float4 accesses 16B-aligned (66 broke odd rows).
#define XTP 68
__global__ void __launch_bounds__(256)
xh_kernel(const float* __restrict__ X) {
    __shared__ float s[64 * XTP];
    const int tid  = threadIdx.x;
    const int mblk = blockIdx.x & 15;    // 16 blocks of 64 m-rows
    const int b    = blockIdx.x >> 4;

    const float* src = X + (size_t)b * NN * NS + (size_t)(mblk * 64) * NS;
#pragma unroll
    for (int i = 0; i < 4; i++) {
        int slot = tid + i * 256;        // 1024 float4 slots
        int row = slot >> 4, j = slot & 15;
        *(float4*)(s + row * XTP + j * 4) = *(const float4*)(src + (size_t)row * NS + j * 4);
    }
    __syncthreads();

    // thread: t = tid>>2 (0..63), m2 group = tid&3 (8 half2 each)
    const int t = tid >> 2;
    const int g = tid & 3;
    uint32_t r[8];
#pragma unroll
    for (int i = 0; i < 8; i++) {
        int ml = 8 * g + i;              // local m2 0..31
        r[i] = pack2(s[(2 * ml) * XTP + t], s[(2 * ml + 1) * XTP + t]);
    }
    uint32_t* dst = (uint32_t*)(g_xh + (size_t)(b * NS + t) * 512 + mblk * 32 + 8 * g);
    *(uint4*)(dst)     = make_uint4(r[0], r[1], r[2], r[3]);
    *(uint4*)(dst + 4) = make_uint4(r[4], r[5], r[6], r[7]);
}

// ---------------- fused prep: blocks [0,8192) = B-convert, [8192,16384) = A-convert ----
__global__ void __launch_bounds__(256)
prep_kernel(const float* __restrict__ G,
            const float* __restrict__ Wu, const float* __restrict__ Wc) {
    const int tid = threadIdx.x;
    if (blockIdx.x < 8192) {
        // ---- B: B[col,k] = h(w[k]) * h(x[k,t]), fragment-permuted ----
        int idx = blockIdx.x * 256 + tid;   // 2,097,152
        int ks  = idx & 3;
        int col = (idx >> 2) & 255;
        int kt  = (idx >> 10) & 15;
        int nt  = (idx >> 14) & 15;
        int b   = idx >> 18;
        int ul = col >> 7, t = (col & 127) >> 1, gate = col & 1;
        int u  = nt * 2 + ul;

        const __half2* xp = g_xh + (size_t)(b * NS + t) * 512 + kt * 32 + ks * 8;
        const float*   wf = (gate ? Wc : Wu) + (size_t)u * NN + kt * 64 + ks * 16;

        float4 f0 = *(const float4*)(wf + 0);
        float4 f1 = *(const float4*)(wf + 4);
        float4 f2 = *(const float4*)(wf + 8);
        float4 f3 = *(const float4*)(wf + 12);
        uint32_t w[8];
        w[0] = pack2(f0.x, f0.y); w[1] = pack2(f0.z, f0.w);
        w[2] = pack2(f1.x, f1.y); w[3] = pack2(f1.z, f1.w);
        w[4] = pack2(f2.x, f2.y); w[5] = pack2(f2.z, f2.w);
        w[6] = pack2(f3.x, f3.y); w[7] = pack2(f3.z, f3.w);

        uint32_t r[8];
#pragma unroll
        for (int j = 0; j < 8; j++) {
            __half2 wv = *reinterpret_cast<__half2*>(&w[j]);
            __half2 v  = __hmul2(wv, xp[j]);
            r[j] = *reinterpret_cast<uint32_t*>(&v);
        }
        uint4 o0 = make_uint4(r[0], r[4], r[1], r[5]);
        uint4 o1 = make_uint4(r[2], r[6], r[3], r[7]);
        uint4* dst = reinterpret_cast<uint4*>(
            g_B + (size_t)((b * 16 + nt) * 16 + kt) * BCHUNK + col * BP + ks * 16);
        dst[0] = o0;
        dst[1] = o1;
    } else {
        // ---- A: half(G), fragment-permuted ----
        int idx = (blockIdx.x - 8192) * 256 + tid;   // 2,097,152 quads
        int q   = idx & 3;
        int ks  = (idx >> 2) & 3;
        int row = (idx >> 4) & 127;
        int kt  = (idx >> 11) & 15;
        int mt  = (idx >> 15) & 7;
        int b   = idx >> 18;
        const float* src = G + ((size_t)b * NN + mt * 128 + row) * NN + kt * 64 + ks * 16 + 2 * q;
        uint2 v;
        v.x = pack2(src[0], src[1]);
        v.y = pack2(src[8], src[9]);
        *reinterpret_cast<uint2*>(
            g_A + (size_t)((b * 8 + mt) * 16 + kt) * ACHUNK + row * AP + ks * 16 + q * 4) = v;
    }
}

// ---------------- main: fp16 HMMA GEMM (3-stage cp.async ring) + fused GRU ----------------
__global__ void __launch_bounds__(256, 1)
gemm_gru_kernel(const float* __restrict__ bu, const float* __restrict__ bc,
                const float* __restrict__ h0)
{
    extern __shared__ __align__(16) char smem[];
    const uint32_t sb = smem_u32(smem);

    const int tid  = threadIdx.x;
    const int wid  = tid >> 5;
    const int lane = tid & 31;
    const int wm   = wid >> 2;
    const int wn   = wid & 3;
    const int grp  = lane >> 2;
    const int qid  = lane & 3;

    const int mt = blockIdx.x;
    const int nt = blockIdx.y;
    const int b  = blockIdx.z;

    const __half* Asrc = g_A + (size_t)((b * 8 + mt) * 16) * ACHUNK;
    const __half* Bsrc = g_B + (size_t)((b * 16 + nt) * 16) * BCHUNK;

    float acc[4][8][4];
#pragma unroll
    for (int i = 0; i < 4; i++)
#pragma unroll
        for (int j = 0; j < 8; j++)
#pragma unroll
            for (int r = 0; r < 4; r++) acc[i][j][r] = 0.f;

#define ISSUE(KT, SLOT) do {                                                       \
    uint32_t sa = sb + (SLOT) * SBYTES;                                            \
    const char* ga = (const char*)(Asrc + (size_t)(KT) * ACHUNK);                  \
    _Pragma("unroll")                                                              \
    for (int i = 0; i < 5; i++)                                                    \
        cp16(sa + tid * 16 + i * 4096, ga + tid * 16 + i * 4096);                  \
    uint32_t sB = sa + ABYTES;                                                     \
    const char* gb = (const char*)(Bsrc + (size_t)(KT) * BCHUNK);                  \
    _Pragma("unroll")                                                              \
    for (int i = 0; i < 10; i++)                                                   \
        cp16(sB + tid * 16 + i * 4096, gb + tid * 16 + i * 4096);                  \
    cp_commit();                                                                   \
} while (0)

#define COMPUTE(SLOT) do {                                                         \
    const __half* Ab = (const __half*)(smem + (SLOT) * SBYTES);                    \
    const __half* Bb = (const __half*)(smem + (SLOT) * SBYTES + ABYTES);           \
    _Pragma("unroll")                                                              \
    for (int ks = 0; ks < 4; ks++) {                                               \
        uint2 alo[4], ahi[4], bf[8];                                               \
        _Pragma("unroll")                                                          \
        for (int mi = 0; mi < 4; mi++) {                                           \
            const __half* ap = Ab + (wm * 64 + mi * 16 + grp) * AP + ks * 16 + qid * 4; \
            alo[mi] = *reinterpret_cast<const uint2*>(ap);                         \
            ahi[mi] = *reinterpret_cast<const uint2*>(ap + 8 * AP);                \
        }                                                                          \
        _Pragma("unroll")                                                          \
        for (int nj = 0; nj < 8; nj++)                                             \
            bf[nj] = *reinterpret_cast<const uint2*>(                              \
                Bb + (wn * 64 + nj * 8 + grp) * BP + ks * 16 + qid * 4);           \
        _Pragma("unroll")                                                          \
        for (int mi = 0; mi < 4; mi++)                                             \
        _Pragma("unroll")                                                          \
        for (int nj = 0; nj < 8; nj++)                                             \
            mma_f16(acc[mi][nj], alo[mi], ahi[mi], bf[nj]);                        \
    }                                                                              \
} while (0)

    // Prologue: stages 0 and 1 in flight
    ISSUE(0, 0);
    ISSUE(1, 1);

    int slot = 0;
#pragma unroll 1
    for (int kt = 0; kt < NKT; kt++) {
        if (kt < NKT - 1) cp_wait<1>();
        else              cp_wait<0>();
        __syncthreads();
        if (kt + 2 < NKT) {
            int ns = slot + 2; if (ns >= STAGES) ns -= STAGES;
            ISSUE(kt + 2, ns);
        }
        COMPUTE(slot);
        if (++slot == STAGES) slot = 0;
    }
    __syncthreads();   // all COMPUTE done before Z aliases staging smem

    // ---- Epilogue: dump Z to smem, run the GRU recurrence over t ----
    float* Zs = (float*)smem;   // [128][ZPITCH]
#pragma unroll
    for (int mi = 0; mi < 4; mi++)
#pragma unroll
        for (int nj = 0; nj < 8; nj++)
#pragma unroll
            for (int r = 0; r < 4; r++) {
                int row = wm * 64 + mi * 16 + grp + ((r >> 1) ? 8 : 0);
                int col = wn * 64 + nj * 8 + qid * 2 + (r & 1);
                Zs[row * ZPITCH + col] = acc[mi][nj][r];
            }
    __syncthreads();

    {
        const int row = tid & 127;
        const int ul  = tid >> 7;
        const int n   = mt * 128 + row;
        const int u   = nt * 2 + ul;
        float h = h0[(size_t)u * NN + n];
        const float buv = bu[u];
        const float bcv = bc[u];
        const float* zrow = Zs + row * ZPITCH + ul * 128;
#pragma unroll 1
        for (int t = 0; t < NS; t++) {
            float zu = zrow[2 * t]     + buv;
            float zc = zrow[2 * t + 1] + bcv;
            float ug = 1.f / (1.f + __expf(-zu));
            float cg = tanhf(zc);
            h = fmaf(ug, h - cg, cg);
        }
        g_h[((size_t)b * NN + n) * NH + u] = h;
    }
#undef ISSUE
#undef COMPUTE
}

// ---------------- prediction head ----------------
#define W1T_PITCH 33
__global__ void __launch_bounds__(256)
head_kernel(const float* __restrict__ W1, const float* __restrict__ b1,
            const float* __restrict__ W2, const float* __restrict__ b2,
            const float* __restrict__ Wd, const float* __restrict__ bd,
            float* __restrict__ out)
{
    __shared__ float w1t[NH * W1T_PITCH];
    __shared__ float w2t[2 * NH * W1T_PITCH];
    __shared__ float b1s[NH], b2s[NH];

    const int tid = threadIdx.x;
    for (int i = tid; i < NH * NH; i += 256) {
        int u = i >> 5, k = i & 31;
        w1t[k * W1T_PITCH + u] = W1[i];
    }
    for (int i = tid; i < NH * 2 * NH; i += 256) {
        int u = i >> 6, k = i & 63;
        w2t[k * W1T_PITCH + u] = W2[i];
    }
    if (tid < NH) { b1s[tid] = b1[tid]; b2s[tid] = b2[tid]; }
    __syncthreads();

    const int warp = (blockIdx.x * blockDim.x + tid) >> 5;
    const int lane = tid & 31;
    if (warp >= NB * NN) return;
    const int b = warp >> 10;
    const int n = warp & (NN - 1);

    const float hv = g_h[((size_t)b * NN + n) * NH + lane];

    float p0 = 0.f, p1 = 0.f, p2 = 0.f, p3 = 0.f;
#pragma unroll
    for (int k = 0; k < NH; k += 4) {
        p0 = fmaf(w1t[(k + 0) * W1T_PITCH + lane], __shfl_sync(0xffffffffu, hv, k + 0), p0);
        p1 = fmaf(w1t[(k + 1) * W1T_PITCH + lane], __shfl_sync(0xffffffffu, hv, k + 1), p1);
        p2 = fmaf(w1t[(k + 2) * W1T_PITCH + lane], __shfl_sync(0xffffffffu, hv, k + 2), p2);
        p3 = fmaf(w1t[(k + 3) * W1T_PITCH + lane], __shfl_sync(0xffffffffu, hv, k + 3), p3);
    }
    float x1 = b1s[lane] + ((p0 + p1) + (p2 + p3));
    x1 = x1 >= 0.f ? x1 : 0.01f * x1;

    float q0 = 0.f, q1 = 0.f, q2 = 0.f, q3 = 0.f;
#pragma unroll
    for (int k = 0; k < NH; k += 4) {
        q0 = fmaf(w2t[(k + 0) * W1T_PITCH + lane], __shfl_sync(0xffffffffu, x1, k + 0), q0);
        q1 = fmaf(w2t[(k + 1) * W1T_PITCH + lane], __shfl_sync(0xffffffffu, x1, k + 1), q1);
        q2 = fmaf(w2t[(k + 2) * W1T_PITCH + lane], __shfl_sync(0xffffffffu, x1, k + 2), q2);
        q3 = fmaf(w2t[(k + 3) * W1T_PITCH + lane], __shfl_sync(0xffffffffu, x1, k + 3), q3);
    }
#pragma unroll
    for (int k = 0; k < NH; k += 4) {
        q0 = fmaf(w2t[(NH + k + 0) * W1T_PITCH + lane], __shfl_sync(0xffffffffu, hv, k + 0), q0);
        q1 = fmaf(w2t[(NH + k + 1) * W1T_PITCH + lane], __shfl_sync(0xffffffffu, hv, k + 1), q1);
        q2 = fmaf(w2t[(NH + k + 2) * W1T_PITCH + lane], __shfl_sync(0xffffffffu, hv, k + 2), q2);
        q3 = fmaf(w2t[(NH + k + 3) * W1T_PITCH + lane], __shfl_sync(0xffffffffu, hv, k + 3), q3);
    }
    float x2 = b2s[lane] + ((q0 + q1) + (q2 + q3));
    x2 = x2 >= 0.f ? x2 : 0.01f * x2;

    float v = Wd[(size_t)n * 2 * NH + lane] * x2
            + Wd[(size_t)n * 2 * NH + NH + lane] * hv;
#pragma unroll
    for (int o = 16; o; o >>= 1) v += __shfl_xor_sync(0xffffffffu, v, o);
    if (lane == 0) out[(size_t)b * NN + n] = v + bd[n];
}

extern "C" void kernel_launch(void* const* d_in, const int* in_sizes, int n_in,
                              void* d_out, int out_size)
{
    (void)in_sizes; (void)n_in; (void)out_size;
    const float* x  = (const float*)d_in[0];
    const float* g  = (const float*)d_in[2];
    const float* Wu = (const float*)d_in[5];
    const float* bu = (const float*)d_in[6];
    const float* Wc = (const float*)d_in[7];
    const float* bc = (const float*)d_in[8];
    const float* h0 = (const float*)d_in[9];
    const float* W1 = (const float*)d_in[10];
    const float* b1 = (const float*)d_in[11];
    const float* W2 = (const float*)d_in[12];
    const float* b2 = (const float*)d_in[13];
    const float* Wd = (const float*)d_in[14];
    const float* bd = (const float*)d_in[15];
    float* out = (float*)d_out;

    xh_kernel<<<NB * 16, 256>>>(x);
    prep_kernel<<<16384, 256>>>(g, Wu, Wc);

    cudaFuncSetAttribute(gemm_gru_kernel,
                         cudaFuncAttributeMaxDynamicSharedMemorySize, SMEM_BYTES);
    dim3 grid(8, 16, NB);
    gemm_gru_kernel<<<grid, 256, SMEM_BYTES>>>(bu, bc, h0);

    head_kernel<<<(NB * NN) / 8, 256>>>(W1, b1, W2, b2, Wd, bd, out);
}